// round 3
// baseline (speedup 1.0000x reference)
#include <cuda_runtime.h>
#include <math.h>
#include <float.h>

#define BB 4
#define TH 120
#define STEPS 8
#define DIN 32
#define DM 512
#define NH 8
#define NL 4
#define DFF 2048
#define NSUB 5
#define DH 64
#define TT 128
#define MR (BB*TT)          /* 512 rows total */
#define SCALE 22.62741699796952f
#define LN_EPS 1e-5f

typedef unsigned long long ull;

// ------------------------- device state -------------------------
__device__ float g_buf[BB*TT*DIN];
__device__ float g_pe[TT*DM];
__device__ float g_h[MR*DM];
__device__ float g_qkv[MR*3*DM];
__device__ float g_qkv2[MR*3*DM];
__device__ float g_attn[MR*DM];
__device__ float g_ff[MR*DFF];
__device__ float g_part[4*MR*DM];
__device__ float g_wqkv[NL*3*DM*DM];
__device__ float g_wembT[DIN*DM];
__device__ float g_weff[DFF*DIN];
__device__ float g_wbemb[DFF];
__device__ float g_vbase[BB*DFF];

__device__ __forceinline__ const float* asel_ptr(int s){
    switch(s){ case 0: return g_h; case 1: return g_attn; default: return g_ff; }
}
__device__ __forceinline__ float* csel_ptr(int s, int z){
    switch(s){ case 0: return z ? g_qkv2 : g_qkv; case 1: return g_ff;
               default: return g_part + (size_t)z*(MR*DM); }
}

__device__ __forceinline__ void ffma2(ull& d, ull a, ull b){
    asm("fma.rn.f32x2 %0, %1, %2, %0;" : "+l"(d) : "l"(a), "l"(b));
}
__device__ __forceinline__ float2 upk(ull v){
    float2 r; asm("mov.b64 {%0,%1}, %2;" : "=f"(r.x), "=f"(r.y) : "l"(v)); return r;
}

__device__ __forceinline__ float gelu_f(float x){
    float u = 0.7978845608028654f*(x + 0.044715f*x*x*x);
    float e = expf(2.0f*u);
    float t = 1.0f - 2.0f/(e + 1.0f);   // tanh(u), robust under fast-math
    return 0.5f*x*(1.0f + t);
}

// ------------------------- precompute kernels -------------------------
__global__ void init_kernel(const float* __restrict__ history){
    int idx = blockIdx.x*blockDim.x + threadIdx.x;
    if (idx >= BB*TT*DIN) return;
    int c = idx % DIN; int t = (idx/DIN) % TT; int b = idx/(DIN*TT);
    g_buf[idx] = (t < TH) ? history[(b*TH + t)*DIN + c] : 0.0f;
}

__global__ void pe_kernel(){
    int idx = blockIdx.x*blockDim.x + threadIdx.x;
    if (idx >= TT*DM) return;
    int t = idx / DM, c = idx % DM;
    int i2 = c & ~1;
    double div = exp((double)i2 * (-9.210340371976184/(double)DM));
    double a = (double)t * div;
    g_pe[idx] = (float)((c & 1) ? cos(a) : sin(a));
}

__global__ void wembT_kernel(const float* __restrict__ W_emb){
    int idx = blockIdx.x*blockDim.x + threadIdx.x;
    if (idx >= DIN*DM) return;
    int k = idx / DM, n = idx % DM;
    g_wembT[idx] = W_emb[n*DIN + k];
}

// Weff = Wr1[:, :512] @ W_emb  (2048 x 32);  wbemb = Wr1[:, :512] @ b_emb
__global__ void weff_kernel(const float* __restrict__ Wr1,
                            const float* __restrict__ W_emb,
                            const float* __restrict__ b_emb){
    int i = blockIdx.x;       // 0..2047
    int j = threadIdx.x;      // 0..31
    float s = 0.f;
    for (int k = 0; k < DM; k++)
        s = fmaf(Wr1[i*(2*DM) + k], W_emb[k*DIN + j], s);
    g_weff[i*DIN + j] = s;
    float t = 0.f;
    for (int k = j; k < DM; k += 32)
        t = fmaf(Wr1[i*(2*DM) + k], b_emb[k], t);
    #pragma unroll
    for (int o = 16; o; o >>= 1) t += __shfl_xor_sync(0xffffffffu, t, o);
    if (j == 0) g_wbemb[i] = t;
}

__global__ void pack_wqkv_kernel(const float* __restrict__ Wq,
                                 const float* __restrict__ Wk,
                                 const float* __restrict__ Wv){
    int idx = blockIdx.x*blockDim.x + threadIdx.x;
    if (idx >= NL*3*DM*DM) return;
    int c = idx % DM; int r = (idx/DM) % (3*DM); int l = idx/(3*DM*DM);
    float v;
    if (r < DM)        v = Wq[(l*DM + r)*DM + c];
    else if (r < 2*DM) v = Wk[(l*DM + (r-DM))*DM + c];
    else               v = Wv[(l*DM + (r-2*DM))*DM + c];
    g_wqkv[idx] = v;
}

// ------------------------- per-step kernels -------------------------
__global__ void embed_kernel(const float* __restrict__ b_emb){
    __shared__ float row[DIN];
    int m = blockIdx.x;            // 0..511 (= b*TT + t)
    int t = m & (TT-1);
    int n = threadIdx.x;           // 0..511
    if (n < DIN) row[n] = g_buf[m*DIN + n];
    __syncthreads();
    float s = 0.f;
    #pragma unroll
    for (int k = 0; k < DIN; k++)
        s = fmaf(row[k], g_wembT[k*DM + n], s);
    g_h[m*DM + n] = (s + b_emb[n])*SCALE + g_pe[t*DM + n];
}

// ---------- f32x2 packed GEMM: BM=128, BN=64, BK=16, 256 threads ----------
// acc packed along M (pairs from As[k][m]); B duplicated in smem as (b,b) pairs.
#define GPA 4
__global__ void __launch_bounds__(256) gemm2_kernel(
        int asel, const float* __restrict__ Wext, int qkv_layer,
        const float* __restrict__ bias, int do_gelu,
        int csel, int Kfull, int Ksub, int ldc){
    __shared__ __align__(16) float As[16][128+GPA];   // [k][m]
    __shared__ __align__(16) float Bs[16][128+GPA];   // [k][2n] duplicated
    const float* A = asel_ptr(asel);
    const float* W = (qkv_layer >= 0) ? (g_wqkv + (size_t)qkv_layer*3*DM*DM) : Wext;
    float* C = csel_ptr(csel, blockIdx.z);
    const int m0 = blockIdx.y*128, n0 = blockIdx.x*64;
    const int kbase = blockIdx.z * Ksub;
    const int tid = threadIdx.x;
    const int tn = tid & 15, tm = tid >> 4;
    const int lRow = tid >> 2, lq = (tid & 3)*4;   // loader: row 0..63, kq 0,4,8,12

    const float* Aptr0 = A + (size_t)(m0 + lRow)*Kfull + kbase + lq;
    const float* Aptr1 = A + (size_t)(m0 + lRow + 64)*Kfull + kbase + lq;
    const float* Wptr  = W + (size_t)(n0 + lRow)*Kfull + kbase + lq;

    ull acc[4][4];
    #pragma unroll
    for (int p = 0; p < 4; p++)
        #pragma unroll
        for (int j = 0; j < 4; j++) acc[p][j] = 0ull;

    const int nIter = Ksub / 16;
    float4 pa0 = *reinterpret_cast<const float4*>(Aptr0);
    float4 pa1 = *reinterpret_cast<const float4*>(Aptr1);
    float4 pb  = *reinterpret_cast<const float4*>(Wptr);

    for (int it = 0; it < nIter; it++){
        // store current regs -> smem
        As[lq+0][lRow] = pa0.x; As[lq+1][lRow] = pa0.y; As[lq+2][lRow] = pa0.z; As[lq+3][lRow] = pa0.w;
        As[lq+0][lRow+64] = pa1.x; As[lq+1][lRow+64] = pa1.y; As[lq+2][lRow+64] = pa1.z; As[lq+3][lRow+64] = pa1.w;
        *reinterpret_cast<float2*>(&Bs[lq+0][2*lRow]) = make_float2(pb.x, pb.x);
        *reinterpret_cast<float2*>(&Bs[lq+1][2*lRow]) = make_float2(pb.y, pb.y);
        *reinterpret_cast<float2*>(&Bs[lq+2][2*lRow]) = make_float2(pb.z, pb.z);
        *reinterpret_cast<float2*>(&Bs[lq+3][2*lRow]) = make_float2(pb.w, pb.w);
        __syncthreads();
        if (it + 1 < nIter){
            int off = (it+1)*16;
            pa0 = *reinterpret_cast<const float4*>(Aptr0 + off);
            pa1 = *reinterpret_cast<const float4*>(Aptr1 + off);
            pb  = *reinterpret_cast<const float4*>(Wptr  + off);
        }
        #pragma unroll
        for (int k = 0; k < 16; k++){
            ulonglong2 a01 = *reinterpret_cast<const ulonglong2*>(&As[k][tm*8]);
            ulonglong2 a23 = *reinterpret_cast<const ulonglong2*>(&As[k][tm*8+4]);
            ulonglong2 b01 = *reinterpret_cast<const ulonglong2*>(&Bs[k][tn*8]);
            ulonglong2 b23 = *reinterpret_cast<const ulonglong2*>(&Bs[k][tn*8+4]);
            ffma2(acc[0][0], a01.x, b01.x); ffma2(acc[0][1], a01.x, b01.y);
            ffma2(acc[0][2], a01.x, b23.x); ffma2(acc[0][3], a01.x, b23.y);
            ffma2(acc[1][0], a01.y, b01.x); ffma2(acc[1][1], a01.y, b01.y);
            ffma2(acc[1][2], a01.y, b23.x); ffma2(acc[1][3], a01.y, b23.y);
            ffma2(acc[2][0], a23.x, b01.x); ffma2(acc[2][1], a23.x, b01.y);
            ffma2(acc[2][2], a23.x, b23.x); ffma2(acc[2][3], a23.x, b23.y);
            ffma2(acc[3][0], a23.y, b01.x); ffma2(acc[3][1], a23.y, b01.y);
            ffma2(acc[3][2], a23.y, b23.x); ffma2(acc[3][3], a23.y, b23.y);
        }
        __syncthreads();
    }
    // epilogue: acc[p][j] = C pair (m = m0+tm*8+2p, +1 ; n = n0+tn*4+j)
    #pragma unroll
    for (int p = 0; p < 4; p++){
        int m = m0 + tm*8 + 2*p;
        #pragma unroll
        for (int j = 0; j < 4; j++){
            int n = n0 + tn*4 + j;
            float2 v = upk(acc[p][j]);
            if (bias){ float bv = bias[n]; v.x += bv; v.y += bv; }
            if (do_gelu){ v.x = gelu_f(v.x); v.y = gelu_f(v.y); }
            C[(size_t)m*ldc + n]     = v.x;
            C[(size_t)(m+1)*ldc + n] = v.y;
        }
    }
}

// attention: one block per (head, batch); 512 threads (16 warps), warp-per-q-row
#define KVP (DH+2)   /* 66: keeps 8B alignment for packed loads */
__global__ void attn_kernel(){
    extern __shared__ float sm[];
    float* qs = sm;                        // [128][64]
    float* ks = sm + TT*DH;                // [128][66]
    float* vs = ks + TT*KVP;               // [128][66]
    float* wb = vs + TT*KVP;               // [16][128]
    int hd = blockIdx.x, b = blockIdx.y;
    int tid = threadIdx.x;
    int wid = tid >> 5, lane = tid & 31;
    for (int i = tid; i < TT*(DH/4); i += 512){
        int t = i/(DH/4), q4 = (i%(DH/4))*4;
        size_t off = (size_t)(b*TT + t)*(3*DM) + hd*DH + q4;
        float4 vq = *reinterpret_cast<const float4*>(g_qkv + off);
        float4 vk = *reinterpret_cast<const float4*>(g_qkv + off + DM);
        float4 vv = *reinterpret_cast<const float4*>(g_qkv + off + 2*DM);
        float4 wq = *reinterpret_cast<const float4*>(g_qkv2 + off);
        float4 wk = *reinterpret_cast<const float4*>(g_qkv2 + off + DM);
        float4 wv = *reinterpret_cast<const float4*>(g_qkv2 + off + 2*DM);
        vq.x+=wq.x; vq.y+=wq.y; vq.z+=wq.z; vq.w+=wq.w;
        vk.x+=wk.x; vk.y+=wk.y; vk.z+=wk.z; vk.w+=wk.w;
        vv.x+=wv.x; vv.y+=wv.y; vv.z+=wv.z; vv.w+=wv.w;
        qs[t*DH+q4+0]=vq.x; qs[t*DH+q4+1]=vq.y; qs[t*DH+q4+2]=vq.z; qs[t*DH+q4+3]=vq.w;
        ks[t*KVP+q4+0]=vk.x; ks[t*KVP+q4+1]=vk.y; ks[t*KVP+q4+2]=vk.z; ks[t*KVP+q4+3]=vk.w;
        vs[t*KVP+q4+0]=vv.x; vs[t*KVP+q4+1]=vv.y; vs[t*KVP+q4+2]=vv.z; vs[t*KVP+q4+3]=vv.w;
    }
    __syncthreads();
    for (int q = wid; q < TT; q += 16){
        const ull* qrow = reinterpret_cast<const ull*>(qs + q*DH);
        float l[4];
        #pragma unroll
        for (int j = 0; j < 4; j++){
            int kr = lane + 32*j;
            const ull* krow = reinterpret_cast<const ull*>(ks + kr*KVP);
            ull a0 = 0ull, a1 = 0ull;
            #pragma unroll
            for (int d = 0; d < 32; d += 2){
                ffma2(a0, qrow[d],   krow[d]);
                ffma2(a1, qrow[d+1], krow[d+1]);
            }
            float2 f0 = upk(a0), f1 = upk(a1);
            float s = (f0.x + f0.y) + (f1.x + f1.y);
            // mask: attend only where k > q (anti-causal, faithful to source).
            // row 127 has no valid k: all lanes -FLT_MAX -> uniform 1/128, matching jax.
            l[j] = (kr > q) ? (s * 0.125f) : -FLT_MAX;
        }
        float mx = fmaxf(fmaxf(l[0],l[1]), fmaxf(l[2],l[3]));
        #pragma unroll
        for (int o = 16; o; o >>= 1) mx = fmaxf(mx, __shfl_xor_sync(0xffffffffu, mx, o));
        float p[4], sum = 0.f;
        #pragma unroll
        for (int j = 0; j < 4; j++){ p[j] = expf(l[j]-mx); sum += p[j]; }
        #pragma unroll
        for (int o = 16; o; o >>= 1) sum += __shfl_xor_sync(0xffffffffu, sum, o);
        float inv = 1.0f/sum;
        #pragma unroll
        for (int j = 0; j < 4; j++) wb[wid*TT + lane + 32*j] = p[j]*inv;
        __syncwarp();
        float o0 = 0.f, o1 = 0.f;
        for (int kr = 0; kr < TT; kr++){
            float w = wb[wid*TT + kr];
            o0 = fmaf(w, vs[kr*KVP+lane],    o0);
            o1 = fmaf(w, vs[kr*KVP+lane+32], o1);
        }
        float* op = g_attn + (size_t)(b*TT+q)*DM + hd*DH;
        op[lane] = o0; op[lane+32] = o1;
    }
}

__device__ __forceinline__ float block_sum256(float v, float* red){
    #pragma unroll
    for (int o = 16; o; o >>= 1) v += __shfl_xor_sync(0xffffffffu, v, o);
    int wid = threadIdx.x >> 5, lane = threadIdx.x & 31;
    if (lane == 0) red[wid] = v;
    __syncthreads();
    if (wid == 0){
        float t = (lane < 8) ? red[lane] : 0.f;
        #pragma unroll
        for (int o = 4; o; o >>= 1) t += __shfl_xor_sync(0xffffffffu, t, o);
        if (lane == 0) red[0] = t;
    }
    __syncthreads();
    float r = red[0];
    __syncthreads();
    return r;
}

// x = h + sum_z part[z] + bias; h <- LN(x)*g + b
__global__ void ln_sum_kernel(int nsplits, const float* __restrict__ bias,
                              const float* __restrict__ gam, const float* __restrict__ bet){
    __shared__ float red[8];
    int m = blockIdx.x, tid = threadIdx.x;      // 256 threads
    float x0 = g_h[(size_t)m*DM + tid];
    float x1 = g_h[(size_t)m*DM + tid + 256];
    for (int z = 0; z < nsplits; z++){
        x0 += g_part[(size_t)z*MR*DM + m*DM + tid];
        x1 += g_part[(size_t)z*MR*DM + m*DM + tid + 256];
    }
    if (bias){ x0 += bias[tid]; x1 += bias[tid+256]; }
    float mu  = block_sum256(x0 + x1, red) * (1.0f/DM);
    float d0 = x0 - mu, d1 = x1 - mu;
    float var = block_sum256(d0*d0 + d1*d1, red) * (1.0f/DM);
    float rstd = 1.0f/sqrtf(var + LN_EPS);
    g_h[(size_t)m*DM + tid]       = d0*rstd*gam[tid]     + bet[tid];
    g_h[(size_t)m*DM + tid + 256] = d1*rstd*gam[tid+256] + bet[tid+256];
}

// vbase[b] = Wr1[:,512:] @ ctx + br1 + SCALE*wbemb;  ctx = h[b, ctx_row]
__global__ void vbase_kernel(const float* __restrict__ Wr1, const float* __restrict__ br1,
                             int ctx_row){
    __shared__ float ctx[DM];
    int b = blockIdx.y;
    int tid = threadIdx.x;     // 128
    for (int i = tid; i < DM; i += 128) ctx[i] = g_h[(size_t)(b*TT + ctx_row)*DM + i];
    __syncthreads();
    int wid = tid >> 5, lane = tid & 31;
    for (int rr = 0; rr < 32; rr++){
        int r = blockIdx.x*128 + wid*32 + rr;
        float s = 0.f;
        for (int k = lane; k < DM; k += 32)
            s = fmaf(Wr1[(size_t)r*(2*DM) + DM + k], ctx[k], s);
        #pragma unroll
        for (int o = 16; o; o >>= 1) s += __shfl_xor_sync(0xffffffffu, s, o);
        if (lane == 0) g_vbase[b*DFF + r] = s + br1[r] + SCALE*g_wbemb[r];
    }
}

// 5 refine substeps entirely in one block per batch (uses Weff folding)
__global__ void refine_kernel(const float* __restrict__ Wr2, const float* __restrict__ br2,
                              float* __restrict__ out, int s){
    __shared__ float cur[DIN];
    __shared__ float hidden[DFF];
    int b = blockIdx.x, tid = threadIdx.x;   // 1024 threads
    int ptr = TH + s;
    if (tid < DIN) cur[tid] = g_buf[(size_t)(b*TT + ptr-1)*DIN + tid];
    __syncthreads();
    int wid = tid >> 5, lane = tid & 31;     // 32 warps == DIN outputs
    for (int it = 0; it < NSUB; it++){
        for (int r = tid; r < DFF; r += 1024){
            float sd = 0.f;
            #pragma unroll
            for (int j = 0; j < DIN; j++)
                sd = fmaf(g_weff[r*DIN + j], cur[j], sd);
            hidden[r] = gelu_f(SCALE*sd + g_vbase[b*DFF + r]);
        }
        __syncthreads();
        float dsum = 0.f;
        for (int k = lane; k < DFF; k += 32)
            dsum = fmaf(Wr2[(size_t)wid*DFF + k], hidden[k], dsum);
        #pragma unroll
        for (int o = 16; o; o >>= 1) dsum += __shfl_xor_sync(0xffffffffu, dsum, o);
        if (lane == 0) cur[wid] += dsum + br2[wid];
        __syncthreads();
    }
    if (tid < DIN){
        float v = cur[tid];
        g_buf[(size_t)(b*TT + ptr)*DIN + tid] = v;
        out[(size_t)(b*STEPS + s)*DIN + tid] = v;
    }
}

// ------------------------- host driver -------------------------
#define ATTN_SMEM ((TT*DH + 2*TT*KVP + 16*TT)*(int)sizeof(float))

extern "C" void kernel_launch(void* const* d_in, const int* in_sizes, int n_in,
                              void* d_out, int out_size){
    const float* history = (const float*)d_in[0];
    /* d_in[1] = steps (always 8, hardcoded) */
    const float* W_emb = (const float*)d_in[2];
    const float* b_emb = (const float*)d_in[3];
    const float* Wq    = (const float*)d_in[4];
    const float* Wk    = (const float*)d_in[5];
    const float* Wv    = (const float*)d_in[6];
    const float* Wo    = (const float*)d_in[7];
    const float* ln1_g = (const float*)d_in[8];
    const float* ln1_b = (const float*)d_in[9];
    const float* W1    = (const float*)d_in[10];
    const float* b1    = (const float*)d_in[11];
    const float* W2    = (const float*)d_in[12];
    const float* b2    = (const float*)d_in[13];
    const float* ln2_g = (const float*)d_in[14];
    const float* ln2_b = (const float*)d_in[15];
    const float* Wr1   = (const float*)d_in[16];
    const float* br1   = (const float*)d_in[17];
    const float* Wr2   = (const float*)d_in[18];
    const float* br2   = (const float*)d_in[19];
    float* out = (float*)d_out;

    cudaFuncSetAttribute(attn_kernel, cudaFuncAttributeMaxDynamicSharedMemorySize, ATTN_SMEM);

    init_kernel<<<(BB*TT*DIN+255)/256, 256>>>(history);
    pe_kernel<<<(TT*DM+255)/256, 256>>>();
    wembT_kernel<<<(DIN*DM+255)/256, 256>>>(W_emb);
    weff_kernel<<<DFF, 32>>>(Wr1, W_emb, b_emb);
    pack_wqkv_kernel<<<(NL*3*DM*DM+255)/256, 256>>>(Wq, Wk, Wv);

    for (int s = 0; s < STEPS; s++){
        embed_kernel<<<MR, DM>>>(b_emb);
        for (int l = 0; l < NL; l++){
            // QKV: [512 x 1536] = h @ packed(Wq,Wk,Wv)^T, split-K=2 (attn sums parts)
            gemm2_kernel<<<dim3(3*DM/64, MR/128, 2), 256>>>(
                0, nullptr, l, nullptr, 0, /*C=qkv parts*/0, DM, DM/2, 3*DM);
            attn_kernel<<<dim3(NH, BB), 512, ATTN_SMEM>>>();
            // proj: attn @ Wo^T, split-K=4 into g_part
            gemm2_kernel<<<dim3(DM/64, MR/128, 4), 256>>>(
                1, Wo + (size_t)l*DM*DM, -1, nullptr, 0, /*C=part*/2, DM, DM/4, DM);
            ln_sum_kernel<<<MR, 256>>>(4, nullptr, ln1_g + l*DM, ln1_b + l*DM);
            // FF1: gelu(h @ W1^T + b1)
            gemm2_kernel<<<dim3(DFF/64, MR/128, 1), 256>>>(
                0, W1 + (size_t)l*DFF*DM, -1, b1 + l*DFF, 1, /*C=ff*/1, DM, DM, DFF);
            // FF2: ff @ W2^T, split-K=4 into g_part
            gemm2_kernel<<<dim3(DM/64, MR/128, 4), 256>>>(
                2, W2 + (size_t)l*DM*DFF, -1, nullptr, 0, /*C=part*/2, DFF, DFF/4, DM);
            ln_sum_kernel<<<MR, 256>>>(4, b2 + l*DM, ln2_g + l*DM, ln2_b + l*DM);
        }
        vbase_kernel<<<dim3(16, BB), 128>>>(Wr1, br1, TH + s - 1);
        refine_kernel<<<BB, 1024>>>(Wr2, br2, out, s);
    }
}

// round 5
// speedup vs baseline: 1.6757x; 1.6757x over previous
#include <cuda_runtime.h>
#include <cuda_bf16.h>
#include <math.h>
#include <float.h>

#define BB 4
#define TH 120
#define STEPS 8
#define DIN 32
#define DM 512
#define NH 8
#define NL 4
#define DFF 2048
#define NSUB 5
#define DH 64
#define TT 128
#define MR (BB*TT)          /* 512 rows total */
#define SCALE 22.62741699796952f
#define LN_EPS 1e-5f

// ------------------------- device state -------------------------
__device__ float g_buf[BB*TT*DIN];
__device__ float g_pe[TT*DM];
__device__ float g_h[MR*DM];
__device__ float g_qkv[MR*3*DM];
__device__ float g_part[4*MR*DM];
__device__ float g_wqkv[NL*3*DM*DM];
__device__ float g_wembT[DIN*DM];
__device__ float g_weff[DFF*DIN];
__device__ float g_wbemb[DFF];
__device__ float g_vbase[BB*DFF];

// bf16 hi/lo split operands for tensor-core GEMMs
__device__ __align__(16) __nv_bfloat16 g_hh[MR*DM],    g_hl[MR*DM];
__device__ __align__(16) __nv_bfloat16 g_attnh[MR*DM], g_attnl[MR*DM];
__device__ __align__(16) __nv_bfloat16 g_ffh[MR*DFF],  g_ffl[MR*DFF];
__device__ __align__(16) __nv_bfloat16 g_wqkvh[NL*3*DM*DM], g_wqkvl[NL*3*DM*DM];
__device__ __align__(16) __nv_bfloat16 g_woh[NL*DM*DM],     g_wol[NL*DM*DM];
__device__ __align__(16) __nv_bfloat16 g_w1h[NL*DFF*DM],    g_w1l[NL*DFF*DM];
__device__ __align__(16) __nv_bfloat16 g_w2h[NL*DM*DFF],    g_w2l[NL*DM*DFF];

__device__ __forceinline__ float gelu_f(float x){
    float u = 0.7978845608028654f*(x + 0.044715f*x*x*x);
    float e = expf(2.0f*u);
    float t = 1.0f - 2.0f/(e + 1.0f);   // tanh(u), robust under fast-math
    return 0.5f*x*(1.0f + t);
}

__device__ __forceinline__ void split_bf16(float x, __nv_bfloat16& h, __nv_bfloat16& l){
    h = __float2bfloat16(x);
    l = __float2bfloat16(x - __bfloat162float(h));
}

// ------------------------- mma helpers -------------------------
__device__ __forceinline__ void ldm4(unsigned* d, unsigned addr){
    asm volatile("ldmatrix.sync.aligned.m8n8.x4.shared.b16 {%0,%1,%2,%3}, [%4];\n"
        : "=r"(d[0]),"=r"(d[1]),"=r"(d[2]),"=r"(d[3]) : "r"(addr));
}
__device__ __forceinline__ void mma16816(float* d, const unsigned* a, const unsigned* b){
    asm volatile("mma.sync.aligned.m16n8k16.row.col.f32.bf16.bf16.f32 "
        "{%0,%1,%2,%3}, {%4,%5,%6,%7}, {%8,%9}, {%0,%1,%2,%3};\n"
        : "+f"(d[0]),"+f"(d[1]),"+f"(d[2]),"+f"(d[3])
        : "r"(a[0]),"r"(a[1]),"r"(a[2]),"r"(a[3]), "r"(b[0]),"r"(b[1]));
}

// ------------------------- precompute kernels -------------------------
__global__ void init_kernel(const float* __restrict__ history){
    int idx = blockIdx.x*blockDim.x + threadIdx.x;
    if (idx >= BB*TT*DIN) return;
    int c = idx % DIN; int t = (idx/DIN) % TT; int b = idx/(DIN*TT);
    g_buf[idx] = (t < TH) ? history[(b*TH + t)*DIN + c] : 0.0f;
}

__global__ void pe_kernel(){
    int idx = blockIdx.x*blockDim.x + threadIdx.x;
    if (idx >= TT*DM) return;
    int t = idx / DM, c = idx % DM;
    int i2 = c & ~1;
    double div = exp((double)i2 * (-9.210340371976184/(double)DM));
    double a = (double)t * div;
    g_pe[idx] = (float)((c & 1) ? cos(a) : sin(a));
}

__global__ void wembT_kernel(const float* __restrict__ W_emb){
    int idx = blockIdx.x*blockDim.x + threadIdx.x;
    if (idx >= DIN*DM) return;
    int k = idx / DM, n = idx % DM;
    g_wembT[idx] = W_emb[n*DIN + k];
}

// Weff = Wr1[:, :512] @ W_emb  (2048 x 32);  wbemb = Wr1[:, :512] @ b_emb
__global__ void weff_kernel(const float* __restrict__ Wr1,
                            const float* __restrict__ W_emb,
                            const float* __restrict__ b_emb){
    int i = blockIdx.x;       // 0..2047
    int j = threadIdx.x;      // 0..31
    float s = 0.f;
    for (int k = 0; k < DM; k++)
        s = fmaf(Wr1[i*(2*DM) + k], W_emb[k*DIN + j], s);
    g_weff[i*DIN + j] = s;
    float t = 0.f;
    for (int k = j; k < DM; k += 32)
        t = fmaf(Wr1[i*(2*DM) + k], b_emb[k], t);
    #pragma unroll
    for (int o = 16; o; o >>= 1) t += __shfl_xor_sync(0xffffffffu, t, o);
    if (j == 0) g_wbemb[i] = t;
}

__global__ void pack_wqkv_kernel(const float* __restrict__ Wq,
                                 const float* __restrict__ Wk,
                                 const float* __restrict__ Wv){
    int idx = blockIdx.x*blockDim.x + threadIdx.x;
    if (idx >= NL*3*DM*DM) return;
    int c = idx % DM; int r = (idx/DM) % (3*DM); int l = idx/(3*DM*DM);
    float v;
    if (r < DM)        v = Wq[(l*DM + r)*DM + c];
    else if (r < 2*DM) v = Wk[(l*DM + (r-DM))*DM + c];
    else               v = Wv[(l*DM + (r-2*DM))*DM + c];
    g_wqkv[idx] = v;
}

__global__ void cvt_kernel(const float* __restrict__ src,
                           __nv_bfloat16* __restrict__ hi,
                           __nv_bfloat16* __restrict__ lo, int n){
    int i = blockIdx.x*blockDim.x + threadIdx.x;
    if (i >= n) return;
    split_bf16(src[i], hi[i], lo[i]);
}

// ------------------------- per-step kernels -------------------------
__global__ void embed_kernel(const float* __restrict__ b_emb){
    __shared__ float row[DIN];
    int m = blockIdx.x;            // 0..511 (= b*TT + t)
    int t = m & (TT-1);
    int n = threadIdx.x;           // 0..511
    if (n < DIN) row[n] = g_buf[m*DIN + n];
    __syncthreads();
    float s = 0.f;
    #pragma unroll
    for (int k = 0; k < DIN; k++)
        s = fmaf(row[k], g_wembT[k*DM + n], s);
    float v = (s + b_emb[n])*SCALE + g_pe[t*DM + n];
    g_h[m*DM + n] = v;
    split_bf16(v, g_hh[m*DM + n], g_hl[m*DM + n]);
}

// ---------- tensor-core GEMM, 3-term bf16 split, fp32 accum ----------
// C[M,N] = A[M,K] * W[N,K]^T, tile 128x64, 256 threads (8 warps, 32x32 each)
#define ASTR 40   /* smem stride in halfs for 32-half rows (+8 pad) */
#define BSTR 40
__global__ void __launch_bounds__(256) gemmT_kernel(
        int asel, const __nv_bfloat16* __restrict__ Bh, const __nv_bfloat16* __restrict__ Bl,
        const float* __restrict__ bias, int csel,
        int Kfull, int Ksub, int ldc){
    __shared__ __align__(16) __nv_bfloat16 sAh[128*ASTR];
    __shared__ __align__(16) __nv_bfloat16 sAl[128*ASTR];
    __shared__ __align__(16) __nv_bfloat16 sBh[64*BSTR];
    __shared__ __align__(16) __nv_bfloat16 sBl[64*BSTR];

    const __nv_bfloat16 *Ah, *Al;
    if (asel == 0){ Ah = g_hh; Al = g_hl; }
    else if (asel == 1){ Ah = g_attnh; Al = g_attnl; }
    else { Ah = g_ffh; Al = g_ffl; }

    const int m0 = blockIdx.y*128, n0 = blockIdx.x*64;
    const int kbase = blockIdx.z*Ksub;
    const int tid = threadIdx.x;

    // global->smem loaders: A 128 rows x 32 halfs (2 uint4/thr), B 64 rows x 32 halfs (1 uint4/thr)
    const int arow = tid >> 1, ac = (tid & 1)*16;
    const int brow = tid >> 2, bc = (tid & 3)*8;
    const __nv_bfloat16* pAh = Ah + (size_t)(m0+arow)*Kfull + kbase + ac;
    const __nv_bfloat16* pAl = Al + (size_t)(m0+arow)*Kfull + kbase + ac;
    const __nv_bfloat16* pBh = Bh + (size_t)(n0+brow)*Kfull + kbase + bc;
    const __nv_bfloat16* pBl = Bl + (size_t)(n0+brow)*Kfull + kbase + bc;

    const int lane = tid & 31, w = tid >> 5;
    const int wm = w & 3, wn = w >> 2;          // warp tile: m 32x4, n 32x2
    const int quad = lane >> 3, r = lane & 7;

    const unsigned baseAh = (unsigned)__cvta_generic_to_shared(sAh);
    const unsigned baseAl = (unsigned)__cvta_generic_to_shared(sAl);
    const unsigned baseBh = (unsigned)__cvta_generic_to_shared(sBh);
    const unsigned baseBl = (unsigned)__cvta_generic_to_shared(sBl);
    // ldmatrix lane addresses (byte offsets); A matrices: (m0-7,k0-7),(m8-15,k0-7),(m0-7,k8-15),(m8-15,k8-15)
    const int aoff = ((wm*32 + (quad&1)*8 + r)*ASTR + (quad>>1)*8)*2;
    // B matrices: (n0-7,k0-7),(n0-7,k8-15),(n8-15,k0-7),(n8-15,k8-15) -> regs = b0,b1 (tile0), b0,b1 (tile1)
    const int boff = ((wn*32 + (quad>>1)*8 + r)*BSTR + (quad&1)*8)*2;

    float acc[2][4][4];
    #pragma unroll
    for (int i = 0; i < 2; i++)
        #pragma unroll
        for (int j = 0; j < 4; j++)
            #pragma unroll
            for (int q = 0; q < 4; q++) acc[i][j][q] = 0.f;

    const int nChunks = Ksub/32;
    uint4 rah0 = *(const uint4*)pAh,     rah1 = *(const uint4*)(pAh+8);
    uint4 ral0 = *(const uint4*)pAl,     ral1 = *(const uint4*)(pAl+8);
    uint4 rbh  = *(const uint4*)pBh,     rbl  = *(const uint4*)pBl;

    for (int ch = 0; ch < nChunks; ch++){
        *(uint4*)&sAh[arow*ASTR + ac]     = rah0;
        *(uint4*)&sAh[arow*ASTR + ac + 8] = rah1;
        *(uint4*)&sAl[arow*ASTR + ac]     = ral0;
        *(uint4*)&sAl[arow*ASTR + ac + 8] = ral1;
        *(uint4*)&sBh[brow*BSTR + bc] = rbh;
        *(uint4*)&sBl[brow*BSTR + bc] = rbl;
        __syncthreads();
        if (ch + 1 < nChunks){
            int o = (ch+1)*32;
            rah0 = *(const uint4*)(pAh+o); rah1 = *(const uint4*)(pAh+o+8);
            ral0 = *(const uint4*)(pAl+o); ral1 = *(const uint4*)(pAl+o+8);
            rbh  = *(const uint4*)(pBh+o); rbl  = *(const uint4*)(pBl+o);
        }
        #pragma unroll
        for (int kk = 0; kk < 32; kk += 16){
            unsigned ah[2][4], al[2][4], bh2[2][4], bl2[2][4];
            ldm4(ah[0], baseAh + aoff + kk*2);
            ldm4(ah[1], baseAh + aoff + (16*ASTR + kk)*2);
            ldm4(al[0], baseAl + aoff + kk*2);
            ldm4(al[1], baseAl + aoff + (16*ASTR + kk)*2);
            ldm4(bh2[0], baseBh + boff + kk*2);
            ldm4(bh2[1], baseBh + boff + (16*BSTR + kk)*2);
            ldm4(bl2[0], baseBl + boff + kk*2);
            ldm4(bl2[1], baseBl + boff + (16*BSTR + kk)*2);
            #pragma unroll
            for (int i = 0; i < 2; i++){
                #pragma unroll
                for (int j = 0; j < 4; j++){
                    const unsigned* bh_ = &bh2[j>>1][(j&1)*2];
                    const unsigned* bl_ = &bl2[j>>1][(j&1)*2];
                    mma16816(acc[i][j], ah[i], bh_);
                    mma16816(acc[i][j], ah[i], bl_);
                    mma16816(acc[i][j], al[i], bh_);
                }
            }
        }
        __syncthreads();
    }

    // epilogue: c0:(g,2t) c1:(g,2t+1) c2:(g+8,2t) c3:(g+8,2t+1)
    const int gid = lane >> 2, tig = lane & 3;
    if (csel == 1){   // FF1: +bias, gelu, write bf16 hi/lo to g_ff (ldc = DFF)
        #pragma unroll
        for (int i = 0; i < 2; i++){
            #pragma unroll
            for (int j = 0; j < 4; j++){
                int m = m0 + wm*32 + i*16 + gid;
                int n = n0 + wn*32 + j*8 + tig*2;
                float bv0 = bias[n], bv1 = bias[n+1];
                float v0 = gelu_f(acc[i][j][0] + bv0);
                float v1 = gelu_f(acc[i][j][1] + bv1);
                float v2 = gelu_f(acc[i][j][2] + bv0);
                float v3 = gelu_f(acc[i][j][3] + bv1);
                __nv_bfloat16 h0,l0,h1,l1,h2,l2,h3,l3;
                split_bf16(v0,h0,l0); split_bf16(v1,h1,l1);
                split_bf16(v2,h2,l2); split_bf16(v3,h3,l3);
                *(__nv_bfloat162*)&g_ffh[(size_t)m*DFF + n]     = __nv_bfloat162(h0,h1);
                *(__nv_bfloat162*)&g_ffl[(size_t)m*DFF + n]     = __nv_bfloat162(l0,l1);
                *(__nv_bfloat162*)&g_ffh[(size_t)(m+8)*DFF + n] = __nv_bfloat162(h2,h3);
                *(__nv_bfloat162*)&g_ffl[(size_t)(m+8)*DFF + n] = __nv_bfloat162(l2,l3);
            }
        }
    } else {
        float* C = (csel == 0) ? g_qkv : (g_part + (size_t)blockIdx.z*(MR*DM));
        #pragma unroll
        for (int i = 0; i < 2; i++){
            #pragma unroll
            for (int j = 0; j < 4; j++){
                int m = m0 + wm*32 + i*16 + gid;
                int n = n0 + wn*32 + j*8 + tig*2;
                *(float2*)&C[(size_t)m*ldc + n]     = make_float2(acc[i][j][0], acc[i][j][1]);
                *(float2*)&C[(size_t)(m+8)*ldc + n] = make_float2(acc[i][j][2], acc[i][j][3]);
            }
        }
    }
}

// attention: one block per (head, batch); 512 threads (16 warps), warp-per-q-row
__global__ void attn_kernel(){
    extern __shared__ float sm[];
    float* qs = sm;                        // [128][64]
    float* ks = sm + TT*DH;                // [128][65]
    float* vs = ks + TT*(DH+1);            // [128][65]
    float* wb = vs + TT*(DH+1);            // [16][128]
    int hd = blockIdx.x, b = blockIdx.y;
    int tid = threadIdx.x;
    int wid = tid >> 5, lane = tid & 31;
    for (int i = tid; i < TT*(DH/4); i += 512){
        int t = i/(DH/4), q4 = (i%(DH/4))*4;
        const float* base = g_qkv + (size_t)(b*TT + t)*(3*DM) + hd*DH + q4;
        float4 vq = *reinterpret_cast<const float4*>(base);
        float4 vk = *reinterpret_cast<const float4*>(base + DM);
        float4 vv = *reinterpret_cast<const float4*>(base + 2*DM);
        qs[t*DH+q4+0]=vq.x; qs[t*DH+q4+1]=vq.y; qs[t*DH+q4+2]=vq.z; qs[t*DH+q4+3]=vq.w;
        ks[t*(DH+1)+q4+0]=vk.x; ks[t*(DH+1)+q4+1]=vk.y; ks[t*(DH+1)+q4+2]=vk.z; ks[t*(DH+1)+q4+3]=vk.w;
        vs[t*(DH+1)+q4+0]=vv.x; vs[t*(DH+1)+q4+1]=vv.y; vs[t*(DH+1)+q4+2]=vv.z; vs[t*(DH+1)+q4+3]=vv.w;
    }
    __syncthreads();
    for (int q = wid; q < TT; q += 16){
        float l[4];
        #pragma unroll
        for (int j = 0; j < 4; j++){
            int kr = lane + 32*j;
            float s = 0.f;
            #pragma unroll
            for (int d = 0; d < DH; d++)
                s = fmaf(qs[q*DH+d], ks[kr*(DH+1)+d], s);
            // mask: attend only where k > q (anti-causal, faithful to source).
            // row 127: all lanes -FLT_MAX -> uniform 1/128, matching jax.
            l[j] = (kr > q) ? (s * 0.125f) : -FLT_MAX;
        }
        float mx = fmaxf(fmaxf(l[0],l[1]), fmaxf(l[2],l[3]));
        #pragma unroll
        for (int o = 16; o; o >>= 1) mx = fmaxf(mx, __shfl_xor_sync(0xffffffffu, mx, o));
        float p[4], sum = 0.f;
        #pragma unroll
        for (int j = 0; j < 4; j++){ p[j] = expf(l[j]-mx); sum += p[j]; }
        #pragma unroll
        for (int o = 16; o; o >>= 1) sum += __shfl_xor_sync(0xffffffffu, sum, o);
        float inv = 1.0f/sum;
        #pragma unroll
        for (int j = 0; j < 4; j++) wb[wid*TT + lane + 32*j] = p[j]*inv;
        __syncwarp();
        float o0 = 0.f, o1 = 0.f;
        for (int kr = 0; kr < TT; kr++){
            float w = wb[wid*TT + kr];
            o0 = fmaf(w, vs[kr*(DH+1)+lane],    o0);
            o1 = fmaf(w, vs[kr*(DH+1)+lane+32], o1);
        }
        size_t op = (size_t)(b*TT+q)*DM + hd*DH;
        split_bf16(o0, g_attnh[op+lane],    g_attnl[op+lane]);
        split_bf16(o1, g_attnh[op+lane+32], g_attnl[op+lane+32]);
    }
}

__device__ __forceinline__ float block_sum256(float v, float* red){
    #pragma unroll
    for (int o = 16; o; o >>= 1) v += __shfl_xor_sync(0xffffffffu, v, o);
    int wid = threadIdx.x >> 5, lane = threadIdx.x & 31;
    if (lane == 0) red[wid] = v;
    __syncthreads();
    if (wid == 0){
        float t = (lane < 8) ? red[lane] : 0.f;
        #pragma unroll
        for (int o = 4; o; o >>= 1) t += __shfl_xor_sync(0xffffffffu, t, o);
        if (lane == 0) red[0] = t;
    }
    __syncthreads();
    float r = red[0];
    __syncthreads();
    return r;
}

// x = h + sum_z part[z] + bias; h <- LN(x)*g + b (fp32 + bf16 hi/lo)
__global__ void ln_sum_kernel(int nsplits, const float* __restrict__ bias,
                              const float* __restrict__ gam, const float* __restrict__ bet){
    __shared__ float red[8];
    int m = blockIdx.x, tid = threadIdx.x;      // 256 threads
    float x0 = g_h[(size_t)m*DM + tid];
    float x1 = g_h[(size_t)m*DM + tid + 256];
    for (int z = 0; z < nsplits; z++){
        x0 += g_part[(size_t)z*MR*DM + m*DM + tid];
        x1 += g_part[(size_t)z*MR*DM + m*DM + tid + 256];
    }
    if (bias){ x0 += bias[tid]; x1 += bias[tid+256]; }
    float mu  = block_sum256(x0 + x1, red) * (1.0f/DM);
    float d0 = x0 - mu, d1 = x1 - mu;
    float var = block_sum256(d0*d0 + d1*d1, red) * (1.0f/DM);
    float rstd = 1.0f/sqrtf(var + LN_EPS);
    float y0 = d0*rstd*gam[tid]     + bet[tid];
    float y1 = d1*rstd*gam[tid+256] + bet[tid+256];
    g_h[(size_t)m*DM + tid]       = y0;
    g_h[(size_t)m*DM + tid + 256] = y1;
    split_bf16(y0, g_hh[(size_t)m*DM + tid],       g_hl[(size_t)m*DM + tid]);
    split_bf16(y1, g_hh[(size_t)m*DM + tid + 256], g_hl[(size_t)m*DM + tid + 256]);
}

// vbase[b] = Wr1[:,512:] @ ctx + br1 + SCALE*wbemb;  ctx = h[b, ctx_row]
__global__ void vbase_kernel(const float* __restrict__ Wr1, const float* __restrict__ br1,
                             int ctx_row){
    __shared__ float ctx[DM];
    int b = blockIdx.y;
    int tid = threadIdx.x;     // 128
    for (int i = tid; i < DM; i += 128) ctx[i] = g_h[(size_t)(b*TT + ctx_row)*DM + i];
    __syncthreads();
    int wid = tid >> 5, lane = tid & 31;
    for (int rr = 0; rr < 32; rr++){
        int r = blockIdx.x*128 + wid*32 + rr;
        float s = 0.f;
        for (int k = lane; k < DM; k += 32)
            s = fmaf(Wr1[(size_t)r*(2*DM) + DM + k], ctx[k], s);
        #pragma unroll
        for (int o = 16; o; o >>= 1) s += __shfl_xor_sync(0xffffffffu, s, o);
        if (lane == 0) g_vbase[b*DFF + r] = s + br1[r] + SCALE*g_wbemb[r];
    }
}

// 5 refine substeps entirely in one block per batch (uses Weff folding)
__global__ void refine_kernel(const float* __restrict__ Wr2, const float* __restrict__ br2,
                              float* __restrict__ out, int s){
    __shared__ float cur[DIN];
    __shared__ float hidden[DFF];
    int b = blockIdx.x, tid = threadIdx.x;   // 1024 threads
    int ptr = TH + s;
    if (tid < DIN) cur[tid] = g_buf[(size_t)(b*TT + ptr-1)*DIN + tid];
    __syncthreads();
    int wid = tid >> 5, lane = tid & 31;     // 32 warps == DIN outputs
    for (int it = 0; it < NSUB; it++){
        for (int r = tid; r < DFF; r += 1024){
            float sd = 0.f;
            #pragma unroll
            for (int j = 0; j < DIN; j++)
                sd = fmaf(g_weff[r*DIN + j], cur[j], sd);
            hidden[r] = gelu_f(SCALE*sd + g_vbase[b*DFF + r]);
        }
        __syncthreads();
        float dsum = 0.f;
        for (int k = lane; k < DFF; k += 32)
            dsum = fmaf(Wr2[(size_t)wid*DFF + k], hidden[k], dsum);
        #pragma unroll
        for (int o = 16; o; o >>= 1) dsum += __shfl_xor_sync(0xffffffffu, dsum, o);
        if (lane == 0) cur[wid] += dsum + br2[wid];
        __syncthreads();
    }
    if (tid < DIN){
        float v = cur[tid];
        g_buf[(size_t)(b*TT + ptr)*DIN + tid] = v;
        out[(size_t)(b*STEPS + s)*DIN + tid] = v;
    }
}

// ------------------------- host driver -------------------------
#define ATTN_SMEM ((TT*DH + 2*TT*(DH+1) + 16*TT)*(int)sizeof(float))

extern "C" void kernel_launch(void* const* d_in, const int* in_sizes, int n_in,
                              void* d_out, int out_size){
    const float* history = (const float*)d_in[0];
    /* d_in[1] = steps (always 8, hardcoded) */
    const float* W_emb = (const float*)d_in[2];
    const float* b_emb = (const float*)d_in[3];
    const float* Wq    = (const float*)d_in[4];
    const float* Wk    = (const float*)d_in[5];
    const float* Wv    = (const float*)d_in[6];
    const float* Wo    = (const float*)d_in[7];
    const float* ln1_g = (const float*)d_in[8];
    const float* ln1_b = (const float*)d_in[9];
    const float* W1    = (const float*)d_in[10];
    const float* b1    = (const float*)d_in[11];
    const float* W2    = (const float*)d_in[12];
    const float* b2    = (const float*)d_in[13];
    const float* ln2_g = (const float*)d_in[14];
    const float* ln2_b = (const float*)d_in[15];
    const float* Wr1   = (const float*)d_in[16];
    const float* br1   = (const float*)d_in[17];
    const float* Wr2   = (const float*)d_in[18];
    const float* br2   = (const float*)d_in[19];
    float* out = (float*)d_out;

    cudaFuncSetAttribute(attn_kernel, cudaFuncAttributeMaxDynamicSharedMemorySize, ATTN_SMEM);

    // weight hi/lo device pointers (resolved from __device__ symbols is not
    // graph-capturable via API; instead pass symbols directly in-kernel).
    init_kernel<<<(BB*TT*DIN+255)/256, 256>>>(history);
    pe_kernel<<<(TT*DM+255)/256, 256>>>();
    wembT_kernel<<<(DIN*DM+255)/256, 256>>>(W_emb);
    weff_kernel<<<DFF, 32>>>(Wr1, W_emb, b_emb);
    pack_wqkv_kernel<<<(NL*3*DM*DM+255)/256, 256>>>(Wq, Wk, Wv);

    // one-time bf16 hi/lo weight conversions (device-symbol dst via small launcher kernels)
    {
        // use cvt_kernel with device-symbol addresses: obtain via separate kernels is
        // unnecessary — device symbols are valid device pointers in device code only,
        // so launch cvt with symbol-selecting wrapper below.
    }
    // wrappers: select dst arrays inside kernels (symbols usable there)
    // implemented as cvt into fixed targets via dedicated launches:
    extern __global__ void cvt_wqkv(const float*);  // fwd decl trick not needed; defined below
    // (definitions after kernel_launch are not allowed; use lambdas pattern instead)

    // Conversions via cvt_kernel using cudaGetSymbolAddress-free approach:
    // cvt_kernel takes raw pointers; device symbol addresses ARE obtainable on host
    // only via cudaGetSymbolAddress (allowed: no allocation). Do that once per call.
    void *wqkvh, *wqkvl, *woh, *wol, *w1h, *w1l, *w2h, *w2l, *wqkvf;
    cudaGetSymbolAddress(&wqkvh, g_wqkvh); cudaGetSymbolAddress(&wqkvl, g_wqkvl);
    cudaGetSymbolAddress(&woh, g_woh);     cudaGetSymbolAddress(&wol, g_wol);
    cudaGetSymbolAddress(&w1h, g_w1h);     cudaGetSymbolAddress(&w1l, g_w1l);
    cudaGetSymbolAddress(&w2h, g_w2h);     cudaGetSymbolAddress(&w2l, g_w2l);
    cudaGetSymbolAddress(&wqkvf, g_wqkv);

    cvt_kernel<<<(NL*3*DM*DM+255)/256, 256>>>((const float*)wqkvf,
        (__nv_bfloat16*)wqkvh, (__nv_bfloat16*)wqkvl, NL*3*DM*DM);
    cvt_kernel<<<(NL*DM*DM+255)/256, 256>>>(Wo,
        (__nv_bfloat16*)woh, (__nv_bfloat16*)wol, NL*DM*DM);
    cvt_kernel<<<(NL*DFF*DM+255)/256, 256>>>(W1,
        (__nv_bfloat16*)w1h, (__nv_bfloat16*)w1l, NL*DFF*DM);
    cvt_kernel<<<(NL*DM*DFF+255)/256, 256>>>(W2,
        (__nv_bfloat16*)w2h, (__nv_bfloat16*)w2l, NL*DM*DFF);

    for (int s = 0; s < STEPS; s++){
        embed_kernel<<<MR, DM>>>(b_emb);
        for (int l = 0; l < NL; l++){
            // QKV: [512 x 1536], K=512, no split (96 blocks)
            gemmT_kernel<<<dim3(3*DM/64, MR/128, 1), 256>>>(
                0, (const __nv_bfloat16*)wqkvh + (size_t)l*3*DM*DM,
                   (const __nv_bfloat16*)wqkvl + (size_t)l*3*DM*DM,
                nullptr, /*csel qkv*/0, DM, DM, 3*DM);
            attn_kernel<<<dim3(NH, BB), 512, ATTN_SMEM>>>();
            // proj: attn @ Wo^T, split-K=4 -> parts
            gemmT_kernel<<<dim3(DM/64, MR/128, 4), 256>>>(
                1, (const __nv_bfloat16*)woh + (size_t)l*DM*DM,
                   (const __nv_bfloat16*)wol + (size_t)l*DM*DM,
                nullptr, /*csel part*/2, DM, DM/4, DM);
            ln_sum_kernel<<<MR, 256>>>(4, nullptr, ln1_g + l*DM, ln1_b + l*DM);
            // FF1: gelu(h @ W1^T + b1) -> ff hi/lo
            gemmT_kernel<<<dim3(DFF/64, MR/128, 1), 256>>>(
                0, (const __nv_bfloat16*)w1h + (size_t)l*DFF*DM,
                   (const __nv_bfloat16*)w1l + (size_t)l*DFF*DM,
                b1 + l*DFF, /*csel ff*/1, DM, DM, DFF);
            // FF2: ff @ W2^T, split-K=4 -> parts
            gemmT_kernel<<<dim3(DM/64, MR/128, 4), 256>>>(
                2, (const __nv_bfloat16*)w2h + (size_t)l*DM*DFF,
                   (const __nv_bfloat16*)w2l + (size_t)l*DM*DFF,
                nullptr, /*csel part*/2, DFF, DFF/4, DM);
            ln_sum_kernel<<<MR, 256>>>(4, b2 + l*DM, ln2_g + l*DM, ln2_b + l*DM);
        }
        vbase_kernel<<<dim3(16, BB), 128>>>(Wr1, br1, TH + s - 1);
        refine_kernel<<<BB, 1024>>>(Wr2, br2, out, s);
    }
}